// round 1
// baseline (speedup 1.0000x reference)
#include <cuda_runtime.h>
#include <math.h>

// ---------------- problem constants ----------------
constexpr int cB = 16, cT = 1024, cD = 256, cH = 2, cDK = 64, cC = 1024;
constexpr int cNT = cB * cT;            // 16384 tokens
constexpr long cTT = (long)cT * cT;     // 1M
constexpr float LN_EPS = 1e-5f;

// ---------------- device scratch (no allocs allowed) ----------------
__device__ float g_q  [cNT * 128];
__device__ float g_k  [cNT * 128];
__device__ float g_v  [cNT * 128];
__device__ float g_ctx[cNT * 128];
__device__ float g_apre[cNT * cD];
__device__ float g_a   [cNT * cD];
__device__ float g_h  [cNT * cC];
__device__ float g_dep[cNT * cC];
__device__ float g_pt [cNT * cC];
__device__ float g_o2 [cNT * cD];
__device__ float g_dwn[cB * 9];
__device__ float g_pwn[cB * cC];

// ---------------- reductions ----------------
__device__ __forceinline__ float warpReduceSum(float v) {
#pragma unroll
    for (int o = 16; o > 0; o >>= 1) v += __shfl_xor_sync(0xffffffffu, v, o);
    return v;
}
__device__ __forceinline__ float warpReduceMax(float v) {
#pragma unroll
    for (int o = 16; o > 0; o >>= 1) v = fmaxf(v, __shfl_xor_sync(0xffffffffu, v, o));
    return v;
}

// ---------------- generic tiled SGEMM ----------------
// out[n,m] = sum_k A[n,k] * B(k,m)     (BT=true: B given row-major [M,K] i.e. W[m*ldb+k];
//                                       BT=false: B row-major [K,M] i.e. B[k*ldb+m])
// Batched via z: off = (z/zdiv)*Q + (z%zdiv)*R for A/B/C; bias/aux shift by (z/zdiv)*Q.
// EPI: 0 none; 1 +bias[m]; 2 +bias[m]+aux[n*ldc+m]; 3 mish(acc+bias[m]);
//      4 acc*aux[m]+bias[m]; 5 acc*0.125
template<bool BT, int EPI>
__global__ void __launch_bounds__(256) gemm_k(
    const float* __restrict__ A, const float* __restrict__ Bm, float* __restrict__ C,
    int M, int N, int Kd, int lda, int ldb, int ldc,
    long aQ, long aR, long bQ, long bR, long cQ, long cR, int zdiv,
    const float* __restrict__ bias, const float* __restrict__ aux,
    long biasQ, long auxQ)
{
    constexpr int BM = 128, BN = 64, BK = 16, TM = 8, TN = 4;
    __shared__ float As[BK][BM + 4];
    __shared__ float Bs[BK][BN + 4];

    int z  = blockIdx.z;
    int zq = z / zdiv, zr = z - zq * zdiv;
    A  += (long)zq * aQ + (long)zr * aR;
    Bm += (long)zq * bQ + (long)zr * bR;
    C  += (long)zq * cQ + (long)zr * cR;
    const float* biasp = bias ? bias + (long)zq * biasQ : nullptr;
    const float* auxp  = aux  ? aux  + (long)zq * auxQ  : nullptr;

    int bm0 = blockIdx.y * BM, bn0 = blockIdx.x * BN;
    int tid = threadIdx.x;
    int tx = tid & 15, ty = tid >> 4;

    float acc[TM][TN];
#pragma unroll
    for (int i = 0; i < TM; i++)
#pragma unroll
        for (int j = 0; j < TN; j++) acc[i][j] = 0.f;

    for (int k0 = 0; k0 < Kd; k0 += BK) {
        // A tile: 128x16 = 512 float4, 2 per thread, store transposed As[k][m]
#pragma unroll
        for (int r = 0; r < 2; r++) {
            int f   = tid + r * 256;
            int row = f >> 2;
            int kq  = f & 3;
            float4 av = *reinterpret_cast<const float4*>(A + (long)(bm0 + row) * lda + k0 + kq * 4);
            As[kq * 4 + 0][row] = av.x; As[kq * 4 + 1][row] = av.y;
            As[kq * 4 + 2][row] = av.z; As[kq * 4 + 3][row] = av.w;
        }
        if (BT) {
            int m = tid >> 2, kq = tid & 3;
            float4 bv = *reinterpret_cast<const float4*>(Bm + (long)(bn0 + m) * ldb + k0 + kq * 4);
            Bs[kq * 4 + 0][m] = bv.x; Bs[kq * 4 + 1][m] = bv.y;
            Bs[kq * 4 + 2][m] = bv.z; Bs[kq * 4 + 3][m] = bv.w;
        } else {
            int kk = tid >> 4, mq = tid & 15;
            float4 bv = *reinterpret_cast<const float4*>(Bm + (long)(k0 + kk) * ldb + bn0 + mq * 4);
            *reinterpret_cast<float4*>(&Bs[kk][mq * 4]) = bv;
        }
        __syncthreads();
#pragma unroll
        for (int kk = 0; kk < BK; kk++) {
            float4 a0 = *reinterpret_cast<const float4*>(&As[kk][ty * TM]);
            float4 a1 = *reinterpret_cast<const float4*>(&As[kk][ty * TM + 4]);
            float4 b0 = *reinterpret_cast<const float4*>(&Bs[kk][tx * TN]);
            float af[TM] = {a0.x, a0.y, a0.z, a0.w, a1.x, a1.y, a1.z, a1.w};
            float bf[TN] = {b0.x, b0.y, b0.z, b0.w};
#pragma unroll
            for (int i = 0; i < TM; i++)
#pragma unroll
                for (int j = 0; j < TN; j++) acc[i][j] += af[i] * bf[j];
        }
        __syncthreads();
    }

    int col0 = bn0 + tx * TN;
#pragma unroll
    for (int i = 0; i < TM; i++) {
        int row = bm0 + ty * TM + i;
        float r[TN];
#pragma unroll
        for (int j = 0; j < TN; j++) {
            float t = acc[i][j];
            if (EPI == 1) t += biasp[col0 + j];
            else if (EPI == 2) t += biasp[col0 + j] + auxp[(long)row * ldc + col0 + j];
            else if (EPI == 3) {
                t += biasp[col0 + j];
                float sp = (t > 20.f) ? t : log1pf(expf(t));
                t = t * tanhf(sp);
            } else if (EPI == 4) t = t * auxp[col0 + j] + biasp[col0 + j];
            else if (EPI == 5) t *= 0.125f;
            r[j] = t;
        }
        float4 v4 = {r[0], r[1], r[2], r[3]};
        *reinterpret_cast<float4*>(C + (long)row * ldc + col0) = v4;
    }
}

// ---------------- softmax (in place on attn rows) ----------------
__global__ void __launch_bounds__(256) softmax_k(float* __restrict__ attn,
                                                 const unsigned char* __restrict__ smask)
{
    int i = blockIdx.x, h = blockIdx.y, b = blockIdx.z;
    float* row = attn + (((long)(b * cH + h)) * cT + i) * cT;
    const unsigned char* mrow = smask + ((long)b * cT + i) * cT;
    int tid = threadIdx.x, lane = tid & 31, wid = tid >> 5;
    __shared__ float red[8];
    __shared__ float bc;

    float v[4];
    float mx = -3.4e38f;
#pragma unroll
    for (int r = 0; r < 4; r++) {
        int j = tid + r * 256;
        float s = row[j];
        if (mrow[j]) s = -1e9f;
        v[r] = s;
        mx = fmaxf(mx, s);
    }
    mx = warpReduceMax(mx);
    if (lane == 0) red[wid] = mx;
    __syncthreads();
    if (wid == 0) {
        float r = (lane < 8) ? red[lane] : -3.4e38f;
        r = warpReduceMax(r);
        if (lane == 0) bc = r;
    }
    __syncthreads();
    mx = bc;
    float sum = 0.f;
#pragma unroll
    for (int r = 0; r < 4; r++) { v[r] = expf(v[r] - mx); sum += v[r]; }
    __syncthreads();
    sum = warpReduceSum(sum);
    if (lane == 0) red[wid] = sum;
    __syncthreads();
    if (wid == 0) {
        float r = (lane < 8) ? red[lane] : 0.f;
        r = warpReduceSum(r);
        if (lane == 0) bc = r;
    }
    __syncthreads();
    float inv = 1.f / bc;
#pragma unroll
    for (int r = 0; r < 4; r++) row[tid + r * 256] = v[r] * inv;
}

// ---------------- LayerNorm over D=256 (one block per token) ----------------
__global__ void __launch_bounds__(256) ln_k(const float* __restrict__ in,
                                            const float* __restrict__ g,
                                            const float* __restrict__ bta,
                                            const unsigned char* __restrict__ mask,
                                            float* __restrict__ out)
{
    long n = blockIdx.x;
    int tid = threadIdx.x, lane = tid & 31, wid = tid >> 5;
    __shared__ float red[8];
    __shared__ float stats[2];

    float x = in[n * cD + tid];
    float s = warpReduceSum(x);
    if (lane == 0) red[wid] = s;
    __syncthreads();
    if (wid == 0) {
        float r = (lane < 8) ? red[lane] : 0.f;
        r = warpReduceSum(r);
        if (lane == 0) stats[0] = r;
    }
    __syncthreads();
    float s2 = warpReduceSum(x * x);
    if (lane == 0) red[wid] = s2;
    __syncthreads();
    if (wid == 0) {
        float r = (lane < 8) ? red[lane] : 0.f;
        r = warpReduceSum(r);
        if (lane == 0) stats[1] = r;
    }
    __syncthreads();
    float mean = stats[0] * (1.f / cD);
    float var  = stats[1] * (1.f / cD) - mean * mean;
    float y = (x - mean) * rsqrtf(var + LN_EPS) * g[tid] + bta[tid];
    if (mask[n]) y = 0.f;
    out[n * cD + tid] = y;
}

// ---------------- depthwise weight inverse norms ----------------
__global__ void __launch_bounds__(128) dwn_k(const float* __restrict__ d_w, float* __restrict__ dwn)
{
    int k = blockIdx.x, b = blockIdx.y;
    int tid = threadIdx.x;
    float s = 0.f;
    for (int c = tid; c < cC; c += 128) {
        float w = d_w[((long)b * cC + c) * 9 + k];
        s += w * w;
    }
    __shared__ float red[4];
    s = warpReduceSum(s);
    if ((tid & 31) == 0) red[tid >> 5] = s;
    __syncthreads();
    if (tid == 0) {
        float r = red[0] + red[1] + red[2] + red[3];
        dwn[b * 9 + k] = 1.f / fmaxf(sqrtf(r), 1e-12f);
    }
}

__global__ void __launch_bounds__(256) pwn_k(const float* __restrict__ p_w, float* __restrict__ pwn)
{
    int c1 = blockIdx.x * 256 + threadIdx.x;
    int b = blockIdx.y;
    const float* base = p_w + (long)b * cC * cC + c1;
    float s = 0.f;
    for (int c2 = 0; c2 < cC; c2++) {
        float w = base[(long)c2 * cC];
        s += w * w;
    }
    pwn[b * cC + c1] = 1.f / fmaxf(sqrtf(s), 1e-12f);
}

// ---------------- depthwise conv (K=9, 'same'), fused scalings ----------------
// dep'[b,t,c] = ((sum_k h[b,t+k-4,c] * d_w[b,c,k]*dwninv[b,k]) * d_g[b,c] + d_b[b,c]) * p_g[b,c]
__global__ void __launch_bounds__(256) conv_k(const float* __restrict__ h,
                                              const float* __restrict__ d_w,
                                              const float* __restrict__ d_g,
                                              const float* __restrict__ d_b,
                                              const float* __restrict__ p_g,
                                              const float* __restrict__ dwn,
                                              float* __restrict__ dep)
{
    int t = blockIdx.x, b = blockIdx.y;
    __shared__ float wk[9];
    if (threadIdx.x < 9) wk[threadIdx.x] = dwn[b * 9 + threadIdx.x];
    __syncthreads();
#pragma unroll
    for (int i = 0; i < 4; i++) {
        int c = threadIdx.x + i * 256;
        const float* wrow = d_w + ((long)b * cC + c) * 9;
        float acc = 0.f;
#pragma unroll
        for (int kk = 0; kk < 9; kk++) {
            int tt = t + kk - 4;
            if (tt >= 0 && tt < cT)
                acc += h[((long)b * cT + tt) * cC + c] * (wrow[kk] * wk[kk]);
        }
        long bc = (long)b * cC + c;
        dep[((long)b * cT + t) * cC + c] = (acc * d_g[bc] + d_b[bc]) * p_g[bc];
    }
}

// ---------------- launch ----------------
extern "C" void kernel_launch(void* const* d_in, const int* in_sizes, int n_in,
                              void* d_out, int out_size)
{
    const float* x    = (const float*)d_in[0];
    const float* d_w  = (const float*)d_in[1];
    const float* d_g  = (const float*)d_in[2];
    const float* d_b  = (const float*)d_in[3];
    const float* p_w  = (const float*)d_in[4];
    const float* p_g  = (const float*)d_in[5];
    const float* p_b  = (const float*)d_in[6];
    const unsigned char* mask  = (const unsigned char*)d_in[7];
    const unsigned char* smask = (const unsigned char*)d_in[8];
    const float* Wq = (const float*)d_in[9];
    const float* bq = (const float*)d_in[10];
    const float* Wk = (const float*)d_in[11];
    const float* bk = (const float*)d_in[12];
    const float* Wv = (const float*)d_in[13];
    const float* bv = (const float*)d_in[14];
    const float* Wo = (const float*)d_in[15];
    const float* bo = (const float*)d_in[16];
    const float* g0 = (const float*)d_in[17];
    const float* b0 = (const float*)d_in[18];
    const float* w1_w = (const float*)d_in[19];
    const float* w1_b = (const float*)d_in[20];
    const float* w2_w = (const float*)d_in[21];
    const float* w2_b = (const float*)d_in[22];
    const float* g1 = (const float*)d_in[23];
    const float* b1 = (const float*)d_in[24];

    float* out  = (float*)d_out;
    float* attn = out + (long)cNT * cD;   // output tuple: (out[B,T,D], attn[B,H,T,T])

    float *q, *k, *v, *ctx, *apre, *a, *h, *dep, *pt, *o2, *dwn, *pwn;
    cudaGetSymbolAddress((void**)&q,   g_q);
    cudaGetSymbolAddress((void**)&k,   g_k);
    cudaGetSymbolAddress((void**)&v,   g_v);
    cudaGetSymbolAddress((void**)&ctx, g_ctx);
    cudaGetSymbolAddress((void**)&apre, g_apre);
    cudaGetSymbolAddress((void**)&a,   g_a);
    cudaGetSymbolAddress((void**)&h,   g_h);
    cudaGetSymbolAddress((void**)&dep, g_dep);
    cudaGetSymbolAddress((void**)&pt,  g_pt);
    cudaGetSymbolAddress((void**)&o2,  g_o2);
    cudaGetSymbolAddress((void**)&dwn, g_dwn);
    cudaGetSymbolAddress((void**)&pwn, g_pwn);

    dim3 blk(256);

    // 1) q,k,v projections: [16384,256] @ [256,128]^T + bias
    gemm_k<true, 1><<<dim3(2, 128, 1), blk>>>(x, Wq, q, cNT, 128, cD, cD, cD, 128,
        0, 0, 0, 0, 0, 0, 1, bq, nullptr, 0, 0);
    gemm_k<true, 1><<<dim3(2, 128, 1), blk>>>(x, Wk, k, cNT, 128, cD, cD, cD, 128,
        0, 0, 0, 0, 0, 0, 1, bk, nullptr, 0, 0);
    gemm_k<true, 1><<<dim3(2, 128, 1), blk>>>(x, Wv, v, cNT, 128, cD, cD, cD, 128,
        0, 0, 0, 0, 0, 0, 1, bv, nullptr, 0, 0);

    // 2) scores = q k^T / 8, batched over (b,h): z=32, zdiv=H
    gemm_k<true, 5><<<dim3(16, 8, 32), blk>>>(q, k, attn, cT, cT, cDK, 128, 128, cT,
        (long)cT * 128, 64, (long)cT * 128, 64, 2 * cTT, cTT, cH, nullptr, nullptr, 0, 0);

    // 3) masked softmax in place (writes final attn output)
    softmax_k<<<dim3(cT, cH, cB), blk>>>(attn, smask);

    // 4) ctx = attn @ v
    gemm_k<false, 0><<<dim3(1, 8, 32), blk>>>(attn, v, ctx, cT, cDK, cT, cT, 128, 128,
        2 * cTT, cTT, (long)cT * 128, 64, (long)cT * 128, 64, cH, nullptr, nullptr, 0, 0);

    // 5) apre = ctx @ Wo^T + bo + x
    gemm_k<true, 2><<<dim3(4, 128, 1), blk>>>(ctx, Wo, apre, cNT, cD, 128, 128, 128, cD,
        0, 0, 0, 0, 0, 0, 1, bo, x, 0, 0);

    // 6) a = LN(apre; g0,b0), masked
    ln_k<<<cNT, blk>>>(apre, g0, b0, mask, a);

    // 7) h = mish(a @ w1^T + w1_b)
    gemm_k<true, 3><<<dim3(16, 128, 1), blk>>>(a, w1_w, h, cNT, cC, cD, cD, cD, cC,
        0, 0, 0, 0, 0, 0, 1, w1_b, nullptr, 0, 0);

    // 8) weight norms
    dwn_k<<<dim3(9, cB), 128>>>(d_w, dwn);
    pwn_k<<<dim3(4, cB), blk>>>(p_w, pwn);

    // 9) depthwise conv + fold d_g, d_b, p_g
    conv_k<<<dim3(cT, cB), blk>>>(h, d_w, d_g, d_b, p_g, dwn, dep);

    // 10) pt = (dep' @ p_w) * pwninv[o] + p_b  (batched over b: 16 x 1024^3)
    gemm_k<false, 4><<<dim3(16, 8, 16), blk>>>(dep, p_w, pt, cT, cC, cC, cC, cC, cC,
        (long)cT * cC, 0, (long)cC * cC, 0, (long)cT * cC, 0, 1, p_b, pwn, cC, cC);

    // 11) o2 = pt @ w2^T + w2_b + a
    gemm_k<true, 2><<<dim3(4, 128, 1), blk>>>(pt, w2_w, o2, cNT, cD, cC, cC, cC, cD,
        0, 0, 0, 0, 0, 0, 1, w2_b, a, 0, 0);

    // 12) out = LN(o2; g1,b1), masked
    ln_k<<<cNT, blk>>>(o2, g1, b1, mask, out);
}